// round 1
// baseline (speedup 1.0000x reference)
#include <cuda_runtime.h>
#include <cstdint>
#include <cstddef>

// Problem constants
#define NBATCH 512
#define MNODE  128
#define NIDX   381   // 3*(M-1)

// Scratch (device globals; allocation is forbidden)
__device__ float g_buf[(size_t)2 * 512 * 512 * 128];   // ping-pong activations
__device__ float g_E[(size_t)512 * 256 * 128];         // embedding output

// ---------------------------------------------------------------------------
// Fused gather + GEMM:  Y[b,o,n] = sum_{c,k} W[o,c*3+k] * X[b,c,idx[b,3(n-1)+k]]
// for n in [1,128); column 0 = 0.  Bias added to columns >= 1.
// Tiling: BM=128 (o), BN=128 (n incl. zero col), BK=8. 256 threads, 8x8 microtile.
// ---------------------------------------------------------------------------
__global__ __launch_bounds__(256, 2) void gemm_tree_kernel(
    const float* __restrict__ X, const float* __restrict__ W,
    const float* __restrict__ bias, const int* __restrict__ idx,
    float* __restrict__ Y, int C, int CK, int O)
{
    __shared__ float sA[8][128];   // W tile  [kk][m]
    __shared__ float sB[8][128];   // gathered tile [kk][n]
    __shared__ int   sIdx[NIDX];

    const int b  = blockIdx.y;
    const int o0 = blockIdx.x * 128;
    const int t  = threadIdx.x;

    for (int i = t; i < NIDX; i += 256) sIdx[i] = idx[b * NIDX + i];

    const float* Xb = X + (size_t)b * C * MNODE;

    float acc[8][8];
#pragma unroll
    for (int j = 0; j < 8; j++)
#pragma unroll
        for (int i = 0; i < 8; i++) acc[j][i] = 0.f;

    const int m_a  = t >> 1;         // A-load: row
    const int ks_a = (t & 1) * 4;    // A-load: kk slot (0 or 4)
    const int tx   = t & 15;
    const int ty   = t >> 4;
    const int nb   = t & 127;        // B-load: column (constant per thread)
    const int gb   = t >> 7;         // B-load: kk base (0 or 1)
    const int jb   = (nb == 0) ? 0 : 3 * (nb - 1);

    __syncthreads();

    for (int ck0 = 0; ck0 < CK; ck0 += 8) {
        // Prefetch into registers (overlaps previous tile's compute)
        float4 w4 = *reinterpret_cast<const float4*>(
            W + (size_t)(o0 + m_a) * CK + ck0 + ks_a);
        float bv[4];
#pragma unroll
        for (int i = 0; i < 4; i++) {
            int ck = ck0 + gb + 2 * i;
            int c  = ck / 3;
            int kr = ck - c * 3;
            bv[i] = (nb == 0) ? 0.f : Xb[c * MNODE + sIdx[jb + kr]];
        }
        __syncthreads();
        sA[ks_a + 0][m_a] = w4.x;
        sA[ks_a + 1][m_a] = w4.y;
        sA[ks_a + 2][m_a] = w4.z;
        sA[ks_a + 3][m_a] = w4.w;
#pragma unroll
        for (int i = 0; i < 4; i++) sB[gb + 2 * i][nb] = bv[i];
        __syncthreads();

#pragma unroll
        for (int kk = 0; kk < 8; kk++) {
            float4 a0 = *reinterpret_cast<const float4*>(&sA[kk][ty * 8]);
            float4 a1 = *reinterpret_cast<const float4*>(&sA[kk][ty * 8 + 4]);
            float4 c0 = *reinterpret_cast<const float4*>(&sB[kk][tx * 8]);
            float4 c1 = *reinterpret_cast<const float4*>(&sB[kk][tx * 8 + 4]);
            float av[8]  = {a0.x, a0.y, a0.z, a0.w, a1.x, a1.y, a1.z, a1.w};
            float bvv[8] = {c0.x, c0.y, c0.z, c0.w, c1.x, c1.y, c1.z, c1.w};
#pragma unroll
            for (int j = 0; j < 8; j++)
#pragma unroll
                for (int i = 0; i < 8; i++) acc[j][i] += av[j] * bvv[i];
        }
    }

    // Epilogue: bias on cols >= 1, col 0 forced to 0.
#pragma unroll
    for (int j = 0; j < 8; j++) {
        int m = o0 + ty * 8 + j;
        float bb = bias[m];
        float* yr = Y + ((size_t)b * O + m) * MNODE + tx * 8;
        float4 v0 = make_float4(acc[j][0] + bb, acc[j][1] + bb,
                                acc[j][2] + bb, acc[j][3] + bb);
        float4 v1 = make_float4(acc[j][4] + bb, acc[j][5] + bb,
                                acc[j][6] + bb, acc[j][7] + bb);
        if (tx == 0) v0.x = 0.f;   // zero column
        *reinterpret_cast<float4*>(yr)     = v0;
        *reinterpret_cast<float4*>(yr + 4) = v1;
    }
}

// ---------------------------------------------------------------------------
// Per-batch LayerNorm over (O=512, M=128) with ddof=1, eps added to std, + ReLU
// ---------------------------------------------------------------------------
__global__ __launch_bounds__(256) void ln_relu_kernel(
    const float* __restrict__ Yin, float* __restrict__ Xout)
{
    const size_t base = (size_t)blockIdx.x * (512 * 128);
    const float4* in4 = reinterpret_cast<const float4*>(Yin + base);
    float4* out4      = reinterpret_cast<float4*>(Xout + base);
    const int N4 = 512 * 128 / 4;   // 16384

    float s = 0.f, s2 = 0.f;
    for (int i = threadIdx.x; i < N4; i += 256) {
        float4 v = in4[i];
        s  += v.x + v.y + v.z + v.w;
        s2 += v.x * v.x + v.y * v.y + v.z * v.z + v.w * v.w;
    }
#pragma unroll
    for (int o = 16; o; o >>= 1) {
        s  += __shfl_xor_sync(0xffffffffu, s,  o);
        s2 += __shfl_xor_sync(0xffffffffu, s2, o);
    }
    __shared__ float rs[8], rs2[8];
    int w = threadIdx.x >> 5;
    if ((threadIdx.x & 31) == 0) { rs[w] = s; rs2[w] = s2; }
    __syncthreads();
    s = 0.f; s2 = 0.f;
#pragma unroll
    for (int i = 0; i < 8; i++) { s += rs[i]; s2 += rs2[i]; }

    const float N = 65536.f;
    float mean = s / N;
    float var  = fmaxf((s2 - s * s / N) * (1.f / 65535.f), 0.f);
    float scale = 1.f / (sqrtf(var) + 1e-5f);

    for (int i = threadIdx.x; i < N4; i += 256) {
        float4 v = in4[i];
        float4 o;
        o.x = fmaxf((v.x - mean) * scale, 0.f);
        o.y = fmaxf((v.y - mean) * scale, 0.f);
        o.z = fmaxf((v.z - mean) * scale, 0.f);
        o.w = fmaxf((v.w - mean) * scale, 0.f);
        out4[i] = o;
    }
}

// ---------------------------------------------------------------------------
// Attention pool + readout MLP. One CTA (256 threads) per batch.
// smem: et[128][257] + gw1 chunk [128][33] + small scratch.
// ---------------------------------------------------------------------------
#define ATTN_SMEM_FLOATS (128 * 257 + 128 * 33 + 256 + 128 + 512 + 128 + 64 + 16)

__global__ __launch_bounds__(256, 1) void attn_head_kernel(
    const float* __restrict__ E,
    const float* __restrict__ gw1, const float* __restrict__ gb1,
    const float* __restrict__ gw2, const float* __restrict__ gb2,
    const float* __restrict__ rw1, const float* __restrict__ rb1,
    const float* __restrict__ rw2, const float* __restrict__ rb2,
    const float* __restrict__ rw3, const float* __restrict__ rb3,
    float* __restrict__ out1, float* __restrict__ outc)
{
    extern __shared__ float sm[];
    float* et   = sm;                  // [128][257]
    float* g1   = et + 128 * 257;      // [128][33] gw1 chunk
    float* gsum = g1 + 128 * 33;       // 256
    float* attn = gsum + 256;          // 128 (unnormalized exp)
    float* comb = attn + 128;          // 512
    float* h1s  = comb + 512;          // 128
    float* h2s  = h1s + 128;           // 64
    float* red  = h2s + 64;            // 16

    const int b = blockIdx.x;
    const int t = threadIdx.x;
    const float* Eb = E + (size_t)b * 256 * 128;

    const int n   = t & 127;
    const int grp = t >> 7;

    // et[n][f] = E[b, f, n]   (coalesced read, conflict-free smem write)
#pragma unroll 4
    for (int i = 0; i < 128; i++) {
        int f = grp + 2 * i;
        et[n * 257 + f] = Eb[f * 128 + n];
    }
    __syncthreads();

    // gate1[n,h] = relu( sum_f et[n,f] * gw1[h,f] + gb1[h] ), accumulated over
    // f-chunks of 32. Thread (n, grp) owns h = grp*64 .. grp*64+63.
    float acc[64];
#pragma unroll
    for (int i = 0; i < 64; i++) acc[i] = 0.f;

    for (int fc = 0; fc < 8; fc++) {
#pragma unroll
        for (int i = 0; i < 16; i++) {
            int e = t + i * 256;
            int h = e >> 5, fj = e & 31;
            g1[h * 33 + fj] = gw1[h * 256 + fc * 32 + fj];
        }
        __syncthreads();
        const float* gbase = g1 + grp * 64 * 33;
        for (int fj = 0; fj < 32; fj++) {
            float ev = et[n * 257 + fc * 32 + fj];
#pragma unroll
            for (int hi = 0; hi < 64; hi++)
                acc[hi] += ev * gbase[hi * 33 + fj];
        }
        __syncthreads();
    }

    float partial = 0.f;
#pragma unroll
    for (int hi = 0; hi < 64; hi++) {
        int h = grp * 64 + hi;
        partial += fmaxf(acc[hi] + gb1[h], 0.f) * gw2[h];
    }
    gsum[t] = partial;
    __syncthreads();

    // softmax over the 128 nodes (threads 0..127)
    if (t < 128) {
        float g = gsum[t] + gsum[t + 128] + gb2[0];
        float m = g;
#pragma unroll
        for (int o = 16; o; o >>= 1) m = fmaxf(m, __shfl_xor_sync(0xffffffffu, m, o));
        if ((t & 31) == 0) red[t >> 5] = m;
        gsum[t] = g;   // stash score
    }
    __syncthreads();
    if (t < 128) {
        float m = fmaxf(fmaxf(red[0], red[1]), fmaxf(red[2], red[3]));
        float e = __expf(gsum[t] - m);
        float ss = e;
#pragma unroll
        for (int o = 16; o; o >>= 1) ss += __shfl_xor_sync(0xffffffffu, ss, o);
        if ((t & 31) == 0) red[4 + (t >> 5)] = ss;
        attn[t] = e;
    }
    __syncthreads();

    // pool + combined (f = t, 0..255)
    {
        float inv = 1.f / (red[4] + red[5] + red[6] + red[7]);
        float p = 0.f;
        for (int nn = 0; nn < 128; nn++) p += attn[nn] * et[nn * 257 + t];
        p *= inv;
        float root = et[1 * 257 + t];
        comb[t] = root;
        comb[256 + t] = p;
        if (outc) {
            outc[(size_t)b * 512 + t]       = root;
            outc[(size_t)b * 512 + 256 + t] = p;
        }
    }
    __syncthreads();

    // MLP: warp-per-output-row dots (coalesced weight reads)
    const int w = t >> 5, lane = t & 31;
    for (int r = w; r < 128; r += 8) {
        float s = 0.f;
        const float* wr = rw1 + r * 512;
        for (int i = lane; i < 512; i += 32) s += comb[i] * wr[i];
#pragma unroll
        for (int o = 16; o; o >>= 1) s += __shfl_xor_sync(0xffffffffu, s, o);
        if (lane == 0) h1s[r] = fmaxf(s + rb1[r], 0.f);
    }
    __syncthreads();
    for (int r = w; r < 64; r += 8) {
        float s = 0.f;
        const float* wr = rw2 + r * 128;
        for (int i = lane; i < 128; i += 32) s += h1s[i] * wr[i];
#pragma unroll
        for (int o = 16; o; o >>= 1) s += __shfl_xor_sync(0xffffffffu, s, o);
        if (lane == 0) h2s[r] = fmaxf(s + rb2[r], 0.f);
    }
    __syncthreads();
    if (w == 0) {
        float s = h2s[lane] * rw3[lane] + h2s[lane + 32] * rw3[lane + 32];
#pragma unroll
        for (int o = 16; o; o >>= 1) s += __shfl_xor_sync(0xffffffffu, s, o);
        if (lane == 0) out1[b] = s + rb3[0];
    }
}

// ---------------------------------------------------------------------------
extern "C" void kernel_launch(void* const* d_in, const int* in_sizes, int n_in,
                              void* d_out, int out_size)
{
    const float* trees   = (const float*)d_in[0];
    const int*   indexes = (const int*)  d_in[1];
    const float* w1  = (const float*)d_in[2];
    const float* b1  = (const float*)d_in[3];
    const float* w2  = (const float*)d_in[4];
    const float* b2  = (const float*)d_in[5];
    const float* w3  = (const float*)d_in[6];
    const float* b3  = (const float*)d_in[7];
    const float* gw1 = (const float*)d_in[8];
    const float* gb1 = (const float*)d_in[9];
    const float* gw2 = (const float*)d_in[10];
    const float* gb2 = (const float*)d_in[11];
    const float* rw1 = (const float*)d_in[12];
    const float* rb1 = (const float*)d_in[13];
    const float* rw2 = (const float*)d_in[14];
    const float* rb2 = (const float*)d_in[15];
    const float* rw3 = (const float*)d_in[16];
    const float* rb3 = (const float*)d_in[17];
    float* out = (float*)d_out;

    float *bufA, *Ebuf;
    cudaGetSymbolAddress((void**)&bufA, g_buf);
    cudaGetSymbolAddress((void**)&Ebuf, g_E);
    float* bufB = bufA + (size_t)512 * 512 * 128;

    // Layer 1: [512 x 600] x [600 x 127]  per batch
    gemm_tree_kernel<<<dim3(4, NBATCH), 256>>>(trees, w1, b1, indexes, bufA, 200, 600, 512);
    ln_relu_kernel<<<NBATCH, 256>>>(bufA, bufB);
    // Layer 2: [512 x 1536] x [1536 x 127]
    gemm_tree_kernel<<<dim3(4, NBATCH), 256>>>(bufB, w2, b2, indexes, bufA, 512, 1536, 512);
    ln_relu_kernel<<<NBATCH, 256>>>(bufA, bufB);
    // Layer 3 (embedding): [256 x 1536] x [1536 x 127]
    gemm_tree_kernel<<<dim3(2, NBATCH), 256>>>(bufB, w3, b3, indexes, Ebuf, 512, 1536, 256);

    // Attention + MLP head
    size_t smem = (size_t)ATTN_SMEM_FLOATS * sizeof(float);
    cudaFuncSetAttribute(attn_head_kernel,
                         cudaFuncAttributeMaxDynamicSharedMemorySize, (int)smem);
    float* outc = (out_size >= 512 + 512 * 512) ? out + 512 : nullptr;
    attn_head_kernel<<<NBATCH, 256, smem>>>(Ebuf, gw1, gb1, gw2, gb2,
                                            rw1, rb1, rw2, rb2, rw3, rb3,
                                            out, outc);
}

// round 3
// speedup vs baseline: 2.7356x; 2.7356x over previous
#include <cuda_runtime.h>
#include <cstdint>
#include <cstddef>

#define NBATCH 512
#define NIDX   381

// ---------------------------------------------------------------------------
// Device scratch (allocation is forbidden)
// ---------------------------------------------------------------------------
__device__ float g_bufA[(size_t)512 * 128 * 512];   // conv out, node-major
__device__ float g_bufB[(size_t)512 * 128 * 512];   // post-LN, node-major
__device__ float g_E  [(size_t)512 * 128 * 256];    // embedding, node-major
__device__ float g_Xt1[(size_t)512 * 128 * 224];    // trees transposed + padded
__device__ uint32_t g_Wf[(size_t)512*672 + (size_t)512*1536 + (size_t)256*1536];

// ---------------------------------------------------------------------------
__device__ __forceinline__ uint32_t f2tf(float f) {
    uint32_t r;
    asm("cvt.rna.tf32.f32 %0, %1;" : "=r"(r) : "f"(f));
    return r;
}

__device__ __forceinline__ void mma_tf32(float* d, const uint32_t* a,
                                         uint32_t b0, uint32_t b1) {
    asm volatile(
        "mma.sync.aligned.m16n8k8.row.col.f32.tf32.tf32.f32 "
        "{%0,%1,%2,%3}, {%4,%5,%6,%7}, {%8,%9}, {%0,%1,%2,%3};"
        : "+f"(d[0]), "+f"(d[1]), "+f"(d[2]), "+f"(d[3])
        : "r"(a[0]), "r"(a[1]), "r"(a[2]), "r"(a[3]), "r"(b0), "r"(b1));
}

// ---------------------------------------------------------------------------
// Weight prep into mma A-fragment order (+ tf32 convert).
// Layout: [o_tile][q][mt(8)][ks(4)][lane(32)][e(4)]
//   g = lane>>2, tid = lane&3
//   o = o_tile*128 + mt*16 + g + (e&1)*8
//   logical k-col = ks*8 + tid + (e>>1)*4 ;  c = cb*32 + kcol, ksel = q/Cdiv
//   value = (c < C) ? W[o][c][ksel] : 0      (W layout [O][C][3])
// ---------------------------------------------------------------------------
__global__ void wfrag_kernel(const float* __restrict__ w, uint32_t* __restrict__ wf,
                             int C, int Cpad, int O) {
    const int Cdiv = Cpad >> 5;
    const int nq = 3 * Cdiv;
    const size_t total = (size_t)O * 3 * Cpad;
    const size_t per_ot = (size_t)nq * 4096;
    for (size_t i = (size_t)blockIdx.x * 256 + threadIdx.x; i < total;
         i += (size_t)gridDim.x * 256) {
        int e    = (int)(i & 3);
        int lane = (int)((i >> 2) & 31);
        int ks   = (int)((i >> 7) & 3);
        int mt   = (int)((i >> 9) & 7);
        int q    = (int)((i >> 12) % nq);
        int ot   = (int)(i / per_ot);
        int g = lane >> 2, tid = lane & 3;
        int ksel = q / Cdiv, cb = q - ksel * Cdiv;
        int o = ot * 128 + mt * 16 + g + (e & 1) * 8;
        int c = cb * 32 + ks * 8 + tid + (e >> 1) * 4;
        float v = (c < C && o < O) ? w[((size_t)o * C + c) * 3 + ksel] : 0.f;
        wf[i] = f2tf(v);
    }
}

// ---------------------------------------------------------------------------
// Transpose trees [B][200][128] -> Xt1 [B][128][224] (zero-padded cols)
// ---------------------------------------------------------------------------
__global__ __launch_bounds__(256) void xpose_kernel(const float* __restrict__ in,
                                                    float* __restrict__ out) {
    __shared__ float tile[32 * 129];
    const int b = blockIdx.x, t = threadIdx.x;
    const float* ib = in + (size_t)b * 200 * 128;
    float* ob = out + (size_t)b * 128 * 224;
    for (int c0 = 0; c0 < 224; c0 += 32) {
#pragma unroll
        for (int i = 0; i < 16; i++) {
            int e = t + i * 256, ci = e >> 7, m = e & 127;
            tile[ci * 129 + m] = (c0 + ci < 200) ? ib[(c0 + ci) * 128 + m] : 0.f;
        }
        __syncthreads();
#pragma unroll
        for (int i = 0; i < 16; i++) {
            int e = t + i * 256, m = e >> 5, ci = e & 31;
            ob[m * 224 + c0 + ci] = tile[ci * 129 + m];
        }
        __syncthreads();
    }
}

// ---------------------------------------------------------------------------
// Gather-fused tf32 mma GEMM.
// Yt[b][n][o0+0..127] = sum_k Wfrag(o,k) * X[b][node(n, ksel)][c]  (+bias, n0=0)
// B smem layout: [n][36] with k-permutation pos = ks*8 + 2*(kk&3) + (kk>>2)
// ---------------------------------------------------------------------------
__global__ __launch_bounds__(256, 2)
void gemm_mma(const float* __restrict__ Xt, const uint32_t* __restrict__ Wf,
              const float* __restrict__ bias, const int* __restrict__ idx,
              float* __restrict__ Yt, int Cstride, int Cdiv, int O)
{
    __shared__ uint32_t sB[2][128 * 36];     // 36864 B
    __shared__ int   sIdx[NIDX + 3];
    __shared__ float sbias[128];

    const int nq = 3 * Cdiv;
    const int b = blockIdx.y, ot = blockIdx.x, o0 = ot * 128;
    const int t = threadIdx.x;
    const int warp = t >> 5, lane = t & 31;
    const int g = lane >> 2, tid = lane & 3;
    const int mq = warp & 3, h = warp >> 2;
    const int mrow = mq * 32, ncol = h * 64;

    for (int i = t; i < NIDX; i += 256) sIdx[i] = idx[b * NIDX + i];
    if (t < 128) sbias[t] = (o0 + t < O) ? bias[o0 + t] : 0.f;

    const float* Xb = Xt + (size_t)b * 128 * Cstride;
    const int rr = t >> 3, l8 = t & 7;
    const int p0 = (l8 >> 1) * 8 + (l8 & 1);

    const uint32_t* Wbase = Wf + (size_t)ot * nq * 4096;

    float acc[2][8][4];
#pragma unroll
    for (int m = 0; m < 2; m++)
#pragma unroll
        for (int j = 0; j < 8; j++)
#pragma unroll
            for (int e = 0; e < 4; e++) acc[m][j][e] = 0.f;

    __syncthreads();

    float4 gv[4];
    // prologue: gather chunk 0
    {
        const int cb = 0;
#pragma unroll
        for (int p = 0; p < 4; p++) {
            int row = rr + 32 * p;
            float4 v = make_float4(0.f, 0.f, 0.f, 0.f);
            if (row) {
                int nd = sIdx[3 * (row - 1) + 0];
                v = *(const float4*)(Xb + (size_t)nd * Cstride + cb * 32 + l8 * 4);
            }
            gv[p] = v;
        }
#pragma unroll
        for (int p = 0; p < 4; p++) {
            uint32_t* r = &sB[0][(rr + 32 * p) * 36];
            r[p0 + 0] = f2tf(gv[p].x);
            r[p0 + 2] = f2tf(gv[p].y);
            r[p0 + 4] = f2tf(gv[p].z);
            r[p0 + 6] = f2tf(gv[p].w);
        }
    }
    __syncthreads();

    for (int q = 0; q < nq; q++) {
        const int s = q & 1;
        // prefetch gather for q+1
        if (q + 1 < nq) {
            int qn = q + 1;
            int kq = qn / Cdiv, cb = qn - kq * Cdiv;
#pragma unroll
            for (int p = 0; p < 4; p++) {
                int row = rr + 32 * p;
                float4 v = make_float4(0.f, 0.f, 0.f, 0.f);
                if (row) {
                    int nd = sIdx[3 * (row - 1) + kq];
                    v = *(const float4*)(Xb + (size_t)nd * Cstride + cb * 32 + l8 * 4);
                }
                gv[p] = v;
            }
        }
        // compute chunk q
        const uint32_t* wq = Wbase + (size_t)q * 4096;
        const uint32_t* bs = &sB[s][0];
#pragma unroll
        for (int ks = 0; ks < 4; ks++) {
            uint4 a0 = *(const uint4*)(wq + ((mq * 2 + 0) * 4 + ks) * 128 + lane * 4);
            uint4 a1 = *(const uint4*)(wq + ((mq * 2 + 1) * 4 + ks) * 128 + lane * 4);
            uint32_t ar0[4] = {a0.x, a0.y, a0.z, a0.w};
            uint32_t ar1[4] = {a1.x, a1.y, a1.z, a1.w};
            uint32_t bf[8][2];
#pragma unroll
            for (int j = 0; j < 8; j++) {
                const uint32_t* bp = bs + (ncol + 8 * j + g) * 36 + ks * 8 + 2 * tid;
                uint2 bv = *(const uint2*)bp;
                bf[j][0] = bv.x; bf[j][1] = bv.y;
            }
#pragma unroll
            for (int j = 0; j < 8; j++) {
                mma_tf32(acc[0][j], ar0, bf[j][0], bf[j][1]);
                mma_tf32(acc[1][j], ar1, bf[j][0], bf[j][1]);
            }
        }
        __syncthreads();
        if (q + 1 < nq) {
            uint32_t* dstb = &sB[s ^ 1][0];
#pragma unroll
            for (int p = 0; p < 4; p++) {
                uint32_t* r = dstb + (rr + 32 * p) * 36;
                r[p0 + 0] = f2tf(gv[p].x);
                r[p0 + 2] = f2tf(gv[p].y);
                r[p0 + 4] = f2tf(gv[p].z);
                r[p0 + 6] = f2tf(gv[p].w);
            }
            __syncthreads();
        }
    }

    // Epilogue: stage each n-half in smem, write node-major
    float* stage = (float*)&sB[0][0];   // [64][132]
    for (int h2 = 0; h2 < 2; h2++) {
        __syncthreads();
        if (h == h2) {
#pragma unroll
            for (int mt = 0; mt < 2; mt++)
#pragma unroll
                for (int j = 0; j < 8; j++) {
                    int nl = 8 * j + 2 * tid;
                    int ol = mrow + mt * 16 + g;
                    stage[nl * 132 + ol]           = acc[mt][j][0];
                    stage[(nl + 1) * 132 + ol]     = acc[mt][j][1];
                    stage[nl * 132 + ol + 8]       = acc[mt][j][2];
                    stage[(nl + 1) * 132 + ol + 8] = acc[mt][j][3];
                }
        }
        __syncthreads();
        {
            const int nl = t >> 2, seg = t & 3;
            const int n = h2 * 64 + nl;
            float* dst = Yt + ((size_t)b * 128 + n) * O + o0 + seg * 32;
#pragma unroll
            for (int v = 0; v < 8; v++) {
                float4 val;
                if (n == 0) val = make_float4(0.f, 0.f, 0.f, 0.f);
                else {
                    val = *(float4*)&stage[nl * 132 + seg * 32 + 4 * v];
                    val.x += sbias[seg * 32 + 4 * v + 0];
                    val.y += sbias[seg * 32 + 4 * v + 1];
                    val.z += sbias[seg * 32 + 4 * v + 2];
                    val.w += sbias[seg * 32 + 4 * v + 3];
                }
                *(float4*)(dst + 4 * v) = val;
            }
        }
    }
}

// ---------------------------------------------------------------------------
// Per-batch LayerNorm (ddof=1, eps on std) + ReLU
// ---------------------------------------------------------------------------
__global__ __launch_bounds__(256) void ln_relu_kernel(
    const float* __restrict__ Yin, float* __restrict__ Xout)
{
    const size_t base = (size_t)blockIdx.x * (512 * 128);
    const float4* in4 = reinterpret_cast<const float4*>(Yin + base);
    float4* out4      = reinterpret_cast<float4*>(Xout + base);
    const int N4 = 512 * 128 / 4;

    float s = 0.f, s2 = 0.f;
    for (int i = threadIdx.x; i < N4; i += 256) {
        float4 v = in4[i];
        s  += v.x + v.y + v.z + v.w;
        s2 += v.x * v.x + v.y * v.y + v.z * v.z + v.w * v.w;
    }
#pragma unroll
    for (int o = 16; o; o >>= 1) {
        s  += __shfl_xor_sync(0xffffffffu, s,  o);
        s2 += __shfl_xor_sync(0xffffffffu, s2, o);
    }
    __shared__ float rs[8], rs2[8];
    int w = threadIdx.x >> 5;
    if ((threadIdx.x & 31) == 0) { rs[w] = s; rs2[w] = s2; }
    __syncthreads();
    s = 0.f; s2 = 0.f;
#pragma unroll
    for (int i = 0; i < 8; i++) { s += rs[i]; s2 += rs2[i]; }

    const float N = 65536.f;
    float mean = s / N;
    float var  = fmaxf((s2 - s * s / N) * (1.f / 65535.f), 0.f);
    float scale = 1.f / (sqrtf(var) + 1e-5f);

    for (int i = threadIdx.x; i < N4; i += 256) {
        float4 v = in4[i];
        float4 o;
        o.x = fmaxf((v.x - mean) * scale, 0.f);
        o.y = fmaxf((v.y - mean) * scale, 0.f);
        o.z = fmaxf((v.z - mean) * scale, 0.f);
        o.w = fmaxf((v.w - mean) * scale, 0.f);
        out4[i] = o;
    }
}

// ---------------------------------------------------------------------------
// Attention pool + readout MLP (E node-major: E[b][n][256])
// ---------------------------------------------------------------------------
#define ATTN_SMEM_FLOATS (128 * 257 + 128 * 33 + 256 + 128 + 512 + 128 + 64 + 16)

__global__ __launch_bounds__(256, 1) void attn_head_kernel(
    const float* __restrict__ E,
    const float* __restrict__ gw1, const float* __restrict__ gb1,
    const float* __restrict__ gw2, const float* __restrict__ gb2,
    const float* __restrict__ rw1, const float* __restrict__ rb1,
    const float* __restrict__ rw2, const float* __restrict__ rb2,
    const float* __restrict__ rw3, const float* __restrict__ rb3,
    float* __restrict__ out1, float* __restrict__ outc)
{
    extern __shared__ float smf[];
    float* et   = smf;
    float* g1   = et + 128 * 257;
    float* gsum = g1 + 128 * 33;
    float* attn = gsum + 256;
    float* comb = attn + 128;
    float* h1s  = comb + 512;
    float* h2s  = h1s + 128;
    float* red  = h2s + 64;

    const int b = blockIdx.x;
    const int t = threadIdx.x;
    const float* Eb = E + (size_t)b * 128 * 256;

    const int n   = t & 127;
    const int grp = t >> 7;

#pragma unroll 4
    for (int i = 0; i < 128; i++)
        et[i * 257 + t] = Eb[i * 256 + t];
    __syncthreads();

    float acc[64];
#pragma unroll
    for (int i = 0; i < 64; i++) acc[i] = 0.f;

    for (int fc = 0; fc < 8; fc++) {
#pragma unroll
        for (int i = 0; i < 16; i++) {
            int e = t + i * 256;
            int hh = e >> 5, fj = e & 31;
            g1[hh * 33 + fj] = gw1[hh * 256 + fc * 32 + fj];
        }
        __syncthreads();
        const float* gbase = g1 + grp * 64 * 33;
        for (int fj = 0; fj < 32; fj++) {
            float ev = et[n * 257 + fc * 32 + fj];
#pragma unroll
            for (int hi = 0; hi < 64; hi++)
                acc[hi] += ev * gbase[hi * 33 + fj];
        }
        __syncthreads();
    }

    float partial = 0.f;
#pragma unroll
    for (int hi = 0; hi < 64; hi++) {
        int hh = grp * 64 + hi;
        partial += fmaxf(acc[hi] + gb1[hh], 0.f) * gw2[hh];
    }
    gsum[t] = partial;
    __syncthreads();

    if (t < 128) {
        float gg = gsum[t] + gsum[t + 128] + gb2[0];
        float m = gg;
#pragma unroll
        for (int o = 16; o; o >>= 1) m = fmaxf(m, __shfl_xor_sync(0xffffffffu, m, o));
        if ((t & 31) == 0) red[t >> 5] = m;
        gsum[t] = gg;
    }
    __syncthreads();
    if (t < 128) {
        float m = fmaxf(fmaxf(red[0], red[1]), fmaxf(red[2], red[3]));
        float e = __expf(gsum[t] - m);
        float ss = e;
#pragma unroll
        for (int o = 16; o; o >>= 1) ss += __shfl_xor_sync(0xffffffffu, ss, o);
        if ((t & 31) == 0) red[4 + (t >> 5)] = ss;
        attn[t] = e;
    }
    __syncthreads();

    {
        float inv = 1.f / (red[4] + red[5] + red[6] + red[7]);
        float p = 0.f;
        for (int nn = 0; nn < 128; nn++) p += attn[nn] * et[nn * 257 + t];
        p *= inv;
        float root = et[1 * 257 + t];
        comb[t] = root;
        comb[256 + t] = p;
        if (outc) {
            outc[(size_t)b * 512 + t]       = root;
            outc[(size_t)b * 512 + 256 + t] = p;
        }
    }
    __syncthreads();

    const int w = t >> 5, lane = t & 31;
    for (int r = w; r < 128; r += 8) {
        float s = 0.f;
        const float* wr = rw1 + r * 512;
        for (int i = lane; i < 512; i += 32) s += comb[i] * wr[i];
#pragma unroll
        for (int o = 16; o; o >>= 1) s += __shfl_xor_sync(0xffffffffu, s, o);
        if (lane == 0) h1s[r] = fmaxf(s + rb1[r], 0.f);
    }
    __syncthreads();
    for (int r = w; r < 64; r += 8) {
        float s = 0.f;
        const float* wr = rw2 + r * 128;
        for (int i = lane; i < 128; i += 32) s += h1s[i] * wr[i];
#pragma unroll
        for (int o = 16; o; o >>= 1) s += __shfl_xor_sync(0xffffffffu, s, o);
        if (lane == 0) h2s[r] = fmaxf(s + rb2[r], 0.f);
    }
    __syncthreads();
    if (w == 0) {
        float s = h2s[lane] * rw3[lane] + h2s[lane + 32] * rw3[lane + 32];
#pragma unroll
        for (int o = 16; o; o >>= 1) s += __shfl_xor_sync(0xffffffffu, s, o);
        if (lane == 0) out1[b] = s + rb3[0];
    }
}

// ---------------------------------------------------------------------------
extern "C" void kernel_launch(void* const* d_in, const int* in_sizes, int n_in,
                              void* d_out, int out_size)
{
    const float* trees   = (const float*)d_in[0];
    const int*   indexes = (const int*)  d_in[1];
    const float* w1  = (const float*)d_in[2];
    const float* b1  = (const float*)d_in[3];
    const float* w2  = (const float*)d_in[4];
    const float* b2  = (const float*)d_in[5];
    const float* w3  = (const float*)d_in[6];
    const float* b3  = (const float*)d_in[7];
    const float* gw1 = (const float*)d_in[8];
    const float* gb1 = (const float*)d_in[9];
    const float* gw2 = (const float*)d_in[10];
    const float* gb2 = (const float*)d_in[11];
    const float* rw1 = (const float*)d_in[12];
    const float* rb1 = (const float*)d_in[13];
    const float* rw2 = (const float*)d_in[14];
    const float* rb2 = (const float*)d_in[15];
    const float* rw3 = (const float*)d_in[16];
    const float* rb3 = (const float*)d_in[17];
    float* out = (float*)d_out;

    float *bufA, *bufB, *Ebuf, *Xt1;
    uint32_t* Wf;
    cudaGetSymbolAddress((void**)&bufA, g_bufA);
    cudaGetSymbolAddress((void**)&bufB, g_bufB);
    cudaGetSymbolAddress((void**)&Ebuf, g_E);
    cudaGetSymbolAddress((void**)&Xt1,  g_Xt1);
    cudaGetSymbolAddress((void**)&Wf,   g_Wf);
    uint32_t* Wf1 = Wf;
    uint32_t* Wf2 = Wf1 + (size_t)512 * 672;
    uint32_t* Wf3 = Wf2 + (size_t)512 * 1536;

    cudaFuncSetAttribute(attn_head_kernel,
                         cudaFuncAttributeMaxDynamicSharedMemorySize,
                         (int)(ATTN_SMEM_FLOATS * sizeof(float)));

    // Prep
    wfrag_kernel<<<512, 256>>>(w1, Wf1, 200, 224, 512);
    wfrag_kernel<<<1024, 256>>>(w2, Wf2, 512, 512, 512);
    wfrag_kernel<<<512, 256>>>(w3, Wf3, 512, 512, 256);
    xpose_kernel<<<NBATCH, 256>>>(trees, Xt1);

    // Layer 1: Cpad=224, Cdiv=7
    gemm_mma<<<dim3(4, NBATCH), 256>>>(Xt1, Wf1, b1, indexes, bufA, 224, 7, 512);
    ln_relu_kernel<<<NBATCH, 256>>>(bufA, bufB);
    // Layer 2: Cdiv=16
    gemm_mma<<<dim3(4, NBATCH), 256>>>(bufB, Wf2, b2, indexes, bufA, 512, 16, 512);
    ln_relu_kernel<<<NBATCH, 256>>>(bufA, bufB);
    // Layer 3 (embedding): O=256
    gemm_mma<<<dim3(2, NBATCH), 256>>>(bufB, Wf3, b3, indexes, Ebuf, 512, 16, 256);

    // Attention + MLP head
    size_t smem = (size_t)ATTN_SMEM_FLOATS * sizeof(float);
    float* outc = (out_size >= 512 + 512 * 512) ? out + 512 : nullptr;
    attn_head_kernel<<<NBATCH, 256, smem>>>(Ebuf, gw1, gb1, gw2, gb2,
                                            rw1, rb1, rw2, rb2, rw3, rb3,
                                            out, outc);
}

// round 4
// speedup vs baseline: 3.8349x; 1.4018x over previous
#include <cuda_runtime.h>
#include <cuda_fp16.h>
#include <cstdint>
#include <cstddef>

#define NBATCH 512
#define NIDX   381

// ---------------------------------------------------------------------------
// Device scratch (allocation is forbidden)
// ---------------------------------------------------------------------------
__device__ float g_bufA[(size_t)512 * 128 * 512];   // conv1 out raw, node-major
__device__ float g_bufB[(size_t)512 * 128 * 512];   // conv2 out raw, node-major
__device__ float g_E  [(size_t)512 * 128 * 256];    // embedding, node-major
__device__ float g_Xt1[(size_t)512 * 128 * 224];    // trees transposed + padded
__device__ uint32_t g_Wf[172032 + 393216 + 196608]; // fp16x2 fragment weights
__device__ float g_stats[2][512 * 4 * 2];           // per-CTA {sum,sumsq} slots

// ---------------------------------------------------------------------------
__device__ __forceinline__ uint32_t pack_h2(float a, float b) {
    __half2 h = __floats2half2_rn(a, b);
    return *reinterpret_cast<uint32_t*>(&h);
}

__device__ __forceinline__ void mma_f16(float* d, const uint32_t* a,
                                        uint32_t b0, uint32_t b1) {
    asm volatile(
        "mma.sync.aligned.m16n8k16.row.col.f32.f16.f16.f32 "
        "{%0,%1,%2,%3}, {%4,%5,%6,%7}, {%8,%9}, {%0,%1,%2,%3};"
        : "+f"(d[0]), "+f"(d[1]), "+f"(d[2]), "+f"(d[3])
        : "r"(a[0]), "r"(a[1]), "r"(a[2]), "r"(a[3]), "r"(b0), "r"(b1));
}

// ---------------------------------------------------------------------------
// Weight prep into fp16 m16n8k16 A-fragment order.
// u32 index decomposition (low->high): e(4), lane(32), s(2), mt(8), q(nq), ot
//   g=lane>>2, tid=lane&3
//   row = ot*128 + mt*16 + g + (e&1)*8
//   c   = cb*32 + s*16 + (tid + (e>>1)*4)*2   (pair {c, c+1})
//   ksel = q / Cdiv, cb = q % Cdiv ;  W layout [O][C][3]
// ---------------------------------------------------------------------------
__global__ void wfrag_kernel(const float* __restrict__ w, uint32_t* __restrict__ wf,
                             int C, int Cpad, int O) {
    const int Cdiv = Cpad >> 5;
    const int nq = 3 * Cdiv;
    const size_t per_ot = (size_t)nq * 2048;
    const size_t total = (size_t)(O >> 7) * per_ot;
    for (size_t i = (size_t)blockIdx.x * 256 + threadIdx.x; i < total;
         i += (size_t)gridDim.x * 256) {
        int e    = (int)(i & 3);
        int lane = (int)((i >> 2) & 31);
        int s    = (int)((i >> 7) & 1);
        int mt   = (int)((i >> 8) & 7);
        int q    = (int)((i >> 11) % nq);
        int ot   = (int)(i / per_ot);
        int g = lane >> 2, tid = lane & 3;
        int ksel = q / Cdiv, cb = q - ksel * Cdiv;
        int row = ot * 128 + mt * 16 + g + (e & 1) * 8;
        int c = cb * 32 + s * 16 + (tid + (e >> 1) * 4) * 2;
        float lo = (c     < C) ? w[((size_t)row * C + c    ) * 3 + ksel] : 0.f;
        float hi = (c + 1 < C) ? w[((size_t)row * C + c + 1) * 3 + ksel] : 0.f;
        wf[i] = pack_h2(lo, hi);
    }
}

// ---------------------------------------------------------------------------
// Transpose trees [B][200][128] -> Xt1 [B][128][224] (zero-padded cols)
// ---------------------------------------------------------------------------
__global__ __launch_bounds__(256) void xpose_kernel(const float* __restrict__ in,
                                                    float* __restrict__ out) {
    __shared__ float tile[32 * 129];
    const int b = blockIdx.x, t = threadIdx.x;
    const float* ib = in + (size_t)b * 200 * 128;
    float* ob = out + (size_t)b * 128 * 224;
    for (int c0 = 0; c0 < 224; c0 += 32) {
#pragma unroll
        for (int i = 0; i < 16; i++) {
            int e = t + i * 256, ci = e >> 7, m = e & 127;
            tile[ci * 129 + m] = (c0 + ci < 200) ? ib[(c0 + ci) * 128 + m] : 0.f;
        }
        __syncthreads();
#pragma unroll
        for (int i = 0; i < 16; i++) {
            int e = t + i * 256, m = e >> 5, ci = e & 31;
            ob[m * 224 + c0 + ci] = tile[ci * 129 + m];
        }
        __syncthreads();
    }
}

// ---------------------------------------------------------------------------
// Gather-fused fp16 mma GEMM with fused input-LN (from stats) and
// output stats production (per-CTA {sum,sumsq} slot).
// ---------------------------------------------------------------------------
__global__ __launch_bounds__(256, 2)
void gemm_mma(const float* __restrict__ X, const uint32_t* __restrict__ Wf,
              const float* __restrict__ bias, const int* __restrict__ idx,
              const float* __restrict__ statsIn, float* __restrict__ statsOut,
              float* __restrict__ Yt, int Cstride, int Cdiv, int O)
{
    __shared__ __align__(16) uint32_t pool[8448];  // sB[2][128*17] | stage[64][132]
    __shared__ int   sIdx[384];
    __shared__ float sbias[128];
    __shared__ float swred[16];

    const int nq = 3 * Cdiv;
    const int b = blockIdx.y, ot = blockIdx.x, o0 = ot * 128;
    const int t = threadIdx.x;
    const int warp = t >> 5, lane = t & 31;
    const int g = lane >> 2, tid = lane & 3;
    const int mq = warp & 3, h = warp >> 2;
    const int mrow = mq * 32, ncol = h * 64;

    for (int i = t; i < NIDX; i += 256) sIdx[i] = idx[b * NIDX + i];
    if (t < 128) sbias[t] = bias[o0 + t];

    // input LN params
    float mean = 0.f, scale = 1.f, relu_lo = -3.0e38f;
    if (statsIn) {
        const float* st = statsIn + b * 8;
        float s = st[0] + st[2] + st[4] + st[6];
        float s2 = st[1] + st[3] + st[5] + st[7];
        const float N = 65536.f;
        mean = s / N;
        float var = fmaxf((s2 - s * s / N) * (1.f / 65535.f), 0.f);
        scale = 1.f / (sqrtf(var) + 1e-5f);
        relu_lo = 0.f;
    }

    const float* Xb = X + (size_t)b * 128 * Cstride;
    const int rr = t >> 3, l8 = t & 7;
    const uint32_t* Wbase = Wf + (size_t)ot * nq * 2048;

    float acc[2][8][4];
#pragma unroll
    for (int m = 0; m < 2; m++)
#pragma unroll
        for (int j = 0; j < 8; j++)
#pragma unroll
            for (int e = 0; e < 4; e++) acc[m][j][e] = 0.f;

    __syncthreads();

    float4 gv[4];
    // prologue: gather chunk 0 (kq=0, cb=0)
#pragma unroll
    for (int p = 0; p < 4; p++) {
        int row = rr + 32 * p;
        float4 v = make_float4(mean, mean, mean, mean);  // -> 0 after transform
        if (row) {
            int nd = sIdx[3 * (row - 1)];
            v = *(const float4*)(Xb + (size_t)nd * Cstride + l8 * 4);
        }
        gv[p] = v;
    }
#pragma unroll
    for (int p = 0; p < 4; p++) {
        float4 v = gv[p];
        v.x = fmaxf((v.x - mean) * scale, relu_lo);
        v.y = fmaxf((v.y - mean) * scale, relu_lo);
        v.z = fmaxf((v.z - mean) * scale, relu_lo);
        v.w = fmaxf((v.w - mean) * scale, relu_lo);
        if (rr + 32 * p == 0) v = make_float4(0.f, 0.f, 0.f, 0.f);
        uint32_t* r = pool + (rr + 32 * p) * 17 + 2 * l8;
        r[0] = pack_h2(v.x, v.y);
        r[1] = pack_h2(v.z, v.w);
    }
    __syncthreads();

    int kq = 0, cb = 0;
    for (int q = 0; q < nq; q++) {
        const int sbuf = q & 1;
        int kn = kq, cbn = cb + 1;
        if (cbn == Cdiv) { cbn = 0; kn++; }
        // prefetch gather for q+1
        if (q + 1 < nq) {
#pragma unroll
            for (int p = 0; p < 4; p++) {
                int row = rr + 32 * p;
                float4 v = make_float4(mean, mean, mean, mean);
                if (row) {
                    int nd = sIdx[3 * (row - 1) + kn];
                    v = *(const float4*)(Xb + (size_t)nd * Cstride + cbn * 32 + l8 * 4);
                }
                gv[p] = v;
            }
        }
        // compute chunk q
        const uint32_t* wq = Wbase + (size_t)q * 2048;
        const uint32_t* bs = pool + sbuf * 2176;
#pragma unroll
        for (int s = 0; s < 2; s++) {
            uint4 A0 = *(const uint4*)(wq + (((mq * 2 + 0) * 2 + s) * 32 + lane) * 4);
            uint4 A1 = *(const uint4*)(wq + (((mq * 2 + 1) * 2 + s) * 32 + lane) * 4);
            uint32_t ar0[4] = {A0.x, A0.y, A0.z, A0.w};
            uint32_t ar1[4] = {A1.x, A1.y, A1.z, A1.w};
            uint32_t bf[8][2];
#pragma unroll
            for (int j = 0; j < 8; j++) {
                const uint32_t* bp = bs + (ncol + 8 * j + g) * 17 + s * 8 + tid;
                bf[j][0] = bp[0];
                bf[j][1] = bp[4];
            }
#pragma unroll
            for (int j = 0; j < 8; j++) {
                mma_f16(acc[0][j], ar0, bf[j][0], bf[j][1]);
                mma_f16(acc[1][j], ar1, bf[j][0], bf[j][1]);
            }
        }
        __syncthreads();
        if (q + 1 < nq) {
            uint32_t* dstb = pool + (sbuf ^ 1) * 2176;
#pragma unroll
            for (int p = 0; p < 4; p++) {
                float4 v = gv[p];
                v.x = fmaxf((v.x - mean) * scale, relu_lo);
                v.y = fmaxf((v.y - mean) * scale, relu_lo);
                v.z = fmaxf((v.z - mean) * scale, relu_lo);
                v.w = fmaxf((v.w - mean) * scale, relu_lo);
                if (rr + 32 * p == 0) v = make_float4(0.f, 0.f, 0.f, 0.f);
                uint32_t* r = dstb + (rr + 32 * p) * 17 + 2 * l8;
                r[0] = pack_h2(v.x, v.y);
                r[1] = pack_h2(v.z, v.w);
            }
            __syncthreads();
        }
        kq = kn; cb = cbn;
    }

    // Epilogue: stage per n-half, write node-major, accumulate output stats
    float* stage = (float*)pool;    // [64][132]
    float psum = 0.f, psq = 0.f;
    for (int h2 = 0; h2 < 2; h2++) {
        __syncthreads();
        if (h == h2) {
#pragma unroll
            for (int mt = 0; mt < 2; mt++)
#pragma unroll
                for (int j = 0; j < 8; j++) {
                    int nl = 8 * j + 2 * tid;
                    int ol = mrow + mt * 16 + g;
                    stage[nl * 132 + ol]           = acc[mt][j][0];
                    stage[(nl + 1) * 132 + ol]     = acc[mt][j][1];
                    stage[nl * 132 + ol + 8]       = acc[mt][j][2];
                    stage[(nl + 1) * 132 + ol + 8] = acc[mt][j][3];
                }
        }
        __syncthreads();
        {
            const int nl = t >> 2, seg = t & 3;
            const int n = h2 * 64 + nl;
            float* dst = Yt + ((size_t)b * 128 + n) * O + o0 + seg * 32;
#pragma unroll
            for (int v = 0; v < 8; v++) {
                float4 val;
                if (n == 0) val = make_float4(0.f, 0.f, 0.f, 0.f);
                else {
                    val = *(float4*)&stage[nl * 132 + seg * 32 + 4 * v];
                    val.x += sbias[seg * 32 + 4 * v + 0];
                    val.y += sbias[seg * 32 + 4 * v + 1];
                    val.z += sbias[seg * 32 + 4 * v + 2];
                    val.w += sbias[seg * 32 + 4 * v + 3];
                }
                psum += val.x + val.y + val.z + val.w;
                psq  += val.x * val.x + val.y * val.y + val.z * val.z + val.w * val.w;
                *(float4*)(dst + 4 * v) = val;
            }
        }
    }

    // deterministic per-CTA stats slot
#pragma unroll
    for (int o = 16; o; o >>= 1) {
        psum += __shfl_xor_sync(0xffffffffu, psum, o);
        psq  += __shfl_xor_sync(0xffffffffu, psq,  o);
    }
    if (lane == 0) { swred[warp] = psum; swred[8 + warp] = psq; }
    __syncthreads();
    if (statsOut && t == 0) {
        float s = 0.f, s2 = 0.f;
#pragma unroll
        for (int i = 0; i < 8; i++) { s += swred[i]; s2 += swred[8 + i]; }
        statsOut[b * 8 + ot * 2]     = s;
        statsOut[b * 8 + ot * 2 + 1] = s2;
    }
}

// ---------------------------------------------------------------------------
// Attention pool + readout MLP (E node-major: E[b][n][256])
// ---------------------------------------------------------------------------
#define ATTN_SMEM_FLOATS (128 * 257 + 128 * 33 + 256 + 128 + 512 + 128 + 64 + 16)

__global__ __launch_bounds__(256, 1) void attn_head_kernel(
    const float* __restrict__ E,
    const float* __restrict__ gw1, const float* __restrict__ gb1,
    const float* __restrict__ gw2, const float* __restrict__ gb2,
    const float* __restrict__ rw1, const float* __restrict__ rb1,
    const float* __restrict__ rw2, const float* __restrict__ rb2,
    const float* __restrict__ rw3, const float* __restrict__ rb3,
    float* __restrict__ out1, float* __restrict__ outc)
{
    extern __shared__ float smf[];
    float* et   = smf;
    float* g1   = et + 128 * 257;
    float* gsum = g1 + 128 * 33;
    float* attn = gsum + 256;
    float* comb = attn + 128;
    float* h1s  = comb + 512;
    float* h2s  = h1s + 128;
    float* red  = h2s + 64;

    const int b = blockIdx.x;
    const int t = threadIdx.x;
    const float* Eb = E + (size_t)b * 128 * 256;

    const int n   = t & 127;
    const int grp = t >> 7;

#pragma unroll 4
    for (int i = 0; i < 128; i++)
        et[i * 257 + t] = Eb[i * 256 + t];
    __syncthreads();

    float acc[64];
#pragma unroll
    for (int i = 0; i < 64; i++) acc[i] = 0.f;

    for (int fc = 0; fc < 8; fc++) {
#pragma unroll
        for (int i = 0; i < 16; i++) {
            int e = t + i * 256;
            int hh = e >> 5, fj = e & 31;
            g1[hh * 33 + fj] = gw1[hh * 256 + fc * 32 + fj];
        }
        __syncthreads();
        const float* gbase = g1 + grp * 64 * 33;
        for (int fj = 0; fj < 32; fj++) {
            float ev = et[n * 257 + fc * 32 + fj];
#pragma unroll
            for (int hi = 0; hi < 64; hi++)
                acc[hi] += ev * gbase[hi * 33 + fj];
        }
        __syncthreads();
    }

    float partial = 0.f;
#pragma unroll
    for (int hi = 0; hi < 64; hi++) {
        int hh = grp * 64 + hi;
        partial += fmaxf(acc[hi] + gb1[hh], 0.f) * gw2[hh];
    }
    gsum[t] = partial;
    __syncthreads();

    if (t < 128) {
        float gg = gsum[t] + gsum[t + 128] + gb2[0];
        float m = gg;
#pragma unroll
        for (int o = 16; o; o >>= 1) m = fmaxf(m, __shfl_xor_sync(0xffffffffu, m, o));
        if ((t & 31) == 0) red[t >> 5] = m;
        gsum[t] = gg;
    }
    __syncthreads();
    if (t < 128) {
        float m = fmaxf(fmaxf(red[0], red[1]), fmaxf(red[2], red[3]));
        float e = __expf(gsum[t] - m);
        float ss = e;
#pragma unroll
        for (int o = 16; o; o >>= 1) ss += __shfl_xor_sync(0xffffffffu, ss, o);
        if ((t & 31) == 0) red[4 + (t >> 5)] = ss;
        attn[t] = e;
    }
    __syncthreads();

    {
        float inv = 1.f / (red[4] + red[5] + red[6] + red[7]);
        float p = 0.f;
        for (int nn = 0; nn < 128; nn++) p += attn[nn] * et[nn * 257 + t];
        p *= inv;
        float root = et[1 * 257 + t];
        comb[t] = root;
        comb[256 + t] = p;
        if (outc) {
            outc[(size_t)b * 512 + t]       = root;
            outc[(size_t)b * 512 + 256 + t] = p;
        }
    }
    __syncthreads();

    const int w = t >> 5, lane = t & 31;
    for (int r = w; r < 128; r += 8) {
        float s = 0.f;
        const float* wr = rw1 + r * 512;
        for (int i = lane; i < 512; i += 32) s += comb[i] * wr[i];
#pragma unroll
        for (int o = 16; o; o >>= 1) s += __shfl_xor_sync(0xffffffffu, s, o);
        if (lane == 0) h1s[r] = fmaxf(s + rb1[r], 0.f);
    }
    __syncthreads();
    for (int r = w; r < 64; r += 8) {
        float s = 0.f;
        const float* wr = rw2 + r * 128;
        for (int i = lane; i < 128; i += 32) s += h1s[i] * wr[i];
#pragma unroll
        for (int o = 16; o; o >>= 1) s += __shfl_xor_sync(0xffffffffu, s, o);
        if (lane == 0) h2s[r] = fmaxf(s + rb2[r], 0.f);
    }
    __syncthreads();
    if (w == 0) {
        float s = h2s[lane] * rw3[lane] + h2s[lane + 32] * rw3[lane + 32];
#pragma unroll
        for (int o = 16; o; o >>= 1) s += __shfl_xor_sync(0xffffffffu, s, o);
        if (lane == 0) out1[b] = s + rb3[0];
    }
}

// ---------------------------------------------------------------------------
extern "C" void kernel_launch(void* const* d_in, const int* in_sizes, int n_in,
                              void* d_out, int out_size)
{
    const float* trees   = (const float*)d_in[0];
    const int*   indexes = (const int*)  d_in[1];
    const float* w1  = (const float*)d_in[2];
    const float* b1  = (const float*)d_in[3];
    const float* w2  = (const float*)d_in[4];
    const float* b2  = (const float*)d_in[5];
    const float* w3  = (const float*)d_in[6];
    const float* b3  = (const float*)d_in[7];
    const float* gw1 = (const float*)d_in[8];
    const float* gb1 = (const float*)d_in[9];
    const float* gw2 = (const float*)d_in[10];
    const float* gb2 = (const float*)d_in[11];
    const float* rw1 = (const float*)d_in[12];
    const float* rb1 = (const float*)d_in[13];
    const float* rw2 = (const float*)d_in[14];
    const float* rb2 = (const float*)d_in[15];
    const float* rw3 = (const float*)d_in[16];
    const float* rb3 = (const float*)d_in[17];
    float* out = (float*)d_out;

    float *bufA, *bufB, *Ebuf, *Xt1, *stats;
    uint32_t* Wf;
    cudaGetSymbolAddress((void**)&bufA, g_bufA);
    cudaGetSymbolAddress((void**)&bufB, g_bufB);
    cudaGetSymbolAddress((void**)&Ebuf, g_E);
    cudaGetSymbolAddress((void**)&Xt1,  g_Xt1);
    cudaGetSymbolAddress((void**)&Wf,   g_Wf);
    cudaGetSymbolAddress((void**)&stats, g_stats);
    uint32_t* Wf1 = Wf;
    uint32_t* Wf2 = Wf1 + 172032;
    uint32_t* Wf3 = Wf2 + 393216;
    float* stats1 = stats;                 // layer-1 output stats
    float* stats2 = stats + 512 * 4 * 2;   // layer-2 output stats

    cudaFuncSetAttribute(attn_head_kernel,
                         cudaFuncAttributeMaxDynamicSharedMemorySize,
                         (int)(ATTN_SMEM_FLOATS * sizeof(float)));

    // Prep
    wfrag_kernel<<<512, 256>>>(w1, Wf1, 200, 224, 512);
    wfrag_kernel<<<1024, 256>>>(w2, Wf2, 512, 512, 512);
    wfrag_kernel<<<512, 256>>>(w3, Wf3, 512, 512, 256);
    xpose_kernel<<<NBATCH, 256>>>(trees, Xt1);

    // Layer 1: raw input (no LN), produce stats1
    gemm_mma<<<dim3(4, NBATCH), 256>>>(Xt1, Wf1, b1, indexes,
                                       nullptr, stats1, bufA, 224, 7, 512);
    // Layer 2: LN(stats1)+ReLU fused on load, produce stats2
    gemm_mma<<<dim3(4, NBATCH), 256>>>(bufA, Wf2, b2, indexes,
                                       stats1, stats2, bufB, 512, 16, 512);
    // Layer 3: LN(stats2)+ReLU fused on load, no stats
    gemm_mma<<<dim3(2, NBATCH), 256>>>(bufB, Wf3, b3, indexes,
                                       stats2, nullptr, Ebuf, 512, 16, 256);

    // Attention + MLP head
    size_t smem = (size_t)ATTN_SMEM_FLOATS * sizeof(float);
    float* outc = (out_size >= 512 + 512 * 512) ? out + 512 : nullptr;
    attn_head_kernel<<<NBATCH, 256, smem>>>(Ebuf, gw1, gb1, gw2, gb2,
                                            rw1, rb1, rw2, rb2, rw3, rb3,
                                            out, outc);
}